// round 11
// baseline (speedup 1.0000x reference)
#include <cuda_runtime.h>
#include <cuda_fp16.h>
#include <cstdint>

// ---------------- problem constants ----------------
#define CIN 128
#define COUT 256
#define NPIX (8 * 128 * 128)
#define M_TOTAL 32768                      // 8 * 64 * 64
#define K_TOTAL 1152                       // 9 * 128
#define FEATS_OUT_ELEMS ((size_t)M_TOTAL * COUT)
#define COORD_OUT_ELEMS ((size_t)M_TOTAL * 3)

// ---------------- GEMM config ----------------
#define BM 128
#define BN 128
#define BK 64                 // k per chunk (fp16)
#define NCHUNK 18             // K_TOTAL / BK
#define NSTAGE 3
#define NTHREADS 512          // 16 warps: 4 m x 4 n, warp tile 32x32

// smem stage: A 128 rows x 128B, then B 128 rows x 128B
// phys16B(chunk) = (chunk ^ (row & 7)) * 16     (8 chunks per row)
#define OFF_B 16384
#define STAGE_BYTES 32768
#define SMEM_TOTAL (NSTAGE * STAGE_BYTES)   // 98304; 2 CTAs/SM -> 192KB/SM

// ---------------- device scratch ----------------
__device__ __align__(16) __half g_Wh[COUT * K_TOTAL];            // [n][k] fp16
__device__ __align__(16) __half g_Ah[(size_t)NPIX * CIN];        // feats fp16

// ---------------- helpers ----------------
__device__ __forceinline__ uint32_t smem_u32(const void* p) {
    uint32_t a;
    asm("{ .reg .u64 t; cvta.to.shared.u64 t, %1; cvt.u32.u64 %0, t; }" : "=r"(a) : "l"(p));
    return a;
}
__device__ __forceinline__ void cp_async16(uint32_t dst, const void* src) {
    asm volatile("cp.async.cg.shared.global [%0], [%1], 16;" :: "r"(dst), "l"(src) : "memory");
}
__device__ __forceinline__ void cp_async16z(uint32_t dst, const void* src, uint32_t src_size) {
    asm volatile("cp.async.cg.shared.global [%0], [%1], 16, %2;"
                 :: "r"(dst), "l"(src), "r"(src_size) : "memory");
}
__device__ __forceinline__ void cp_commit() {
    asm volatile("cp.async.commit_group;" ::: "memory");
}
template <int N>
__device__ __forceinline__ void cp_wait() {
    asm volatile("cp.async.wait_group %0;" :: "n"(N) : "memory");
}
__device__ __forceinline__ void ldsm_x4(uint32_t& r0, uint32_t& r1, uint32_t& r2, uint32_t& r3,
                                        uint32_t addr) {
    asm volatile("ldmatrix.sync.aligned.m8n8.x4.shared.b16 {%0,%1,%2,%3}, [%4];"
                 : "=r"(r0), "=r"(r1), "=r"(r2), "=r"(r3) : "r"(addr));
}
__device__ __forceinline__ void mma16816(float* c, const uint32_t* a, uint32_t b0, uint32_t b1) {
    asm volatile("mma.sync.aligned.m16n8k16.row.col.f32.f16.f16.f32 "
                 "{%0,%1,%2,%3}, {%4,%5,%6,%7}, {%8,%9}, {%0,%1,%2,%3};"
                 : "+f"(c[0]), "+f"(c[1]), "+f"(c[2]), "+f"(c[3])
                 : "r"(a[0]), "r"(a[1]), "r"(a[2]), "r"(a[3]), "r"(b0), "r"(b1));
}

// ---------------- fused prep: feats fp32->fp16 stream + weight transpose ----------------
#define A4_TOTAL ((size_t)NPIX * CIN / 4)
#define A4_BLOCKS 16384
__global__ __launch_bounds__(256)
void prep_kernel(const float* __restrict__ feats, const float* __restrict__ w) {
    __shared__ float tile[32][33];
    if (blockIdx.x < A4_BLOCKS) {
        size_t i4 = (size_t)blockIdx.x * 256 + threadIdx.x;
        float4 v = reinterpret_cast<const float4*>(feats)[i4];
        __half2 h0 = __floats2half2_rn(v.x, v.y);
        __half2 h1 = __floats2half2_rn(v.z, v.w);
        reinterpret_cast<uint2*>(g_Ah)[i4] =
            make_uint2(*reinterpret_cast<uint32_t*>(&h0), *reinterpret_cast<uint32_t*>(&h1));
    } else {
        const int bid = blockIdx.x - A4_BLOCKS;      // 0..287
        const int kt = bid % (K_TOTAL / 32);
        const int nt = bid / (K_TOTAL / 32);
        const int ty = threadIdx.x >> 5, tx = threadIdx.x & 31;
        #pragma unroll
        for (int j = 0; j < 4; ++j)
            tile[ty + j * 8][tx] = w[(size_t)(kt * 32 + ty + j * 8) * COUT + nt * 32 + tx];
        __syncthreads();
        #pragma unroll
        for (int j = 0; j < 4; ++j) {
            const int nr = nt * 32 + ty + j * 8;
            const int k  = kt * 32 + tx;
            g_Wh[(size_t)nr * K_TOTAL + k] = __float2half_rn(tile[tx][ty + j * 8]);
        }
    }
}

// ---------------- main GEMM kernel ----------------
__global__ __launch_bounds__(NTHREADS, 2)
void conv_mma_kernel(const float* __restrict__ alpha,
                     float* __restrict__ out)
{
    extern __shared__ char smem[];
    const uint32_t sb = smem_u32(smem);
    const int tid = threadIdx.x;
    const int w = tid >> 5, l = tid & 31;
    const int mblk = blockIdx.x, nblk = blockIdx.y;
    const int wm = w & 3, wn = w >> 2;      // 4m x 4n, warp tile 32x32

    if (nblk == 0) {
        if (tid < 128) {
            int p = mblk * 128 + tid;
            float* row = out + FEATS_OUT_ELEMS + (size_t)p * 3;
            row[0] = (float)(p >> 12);
            row[1] = (float)((p & 4095) >> 6);
            row[2] = (float)(p & 63);
        }
        if (mblk == 0 && tid == 128)
            out[FEATS_OUT_ELEMS + COORD_OUT_ELEMS] = alpha[0];
    }

    // ---- loader geometry: thread -> row tid>>2, two 16B segs 2*(tid&3)+{0,1}
    const int lrow = tid >> 2;
    const int s0   = (tid & 3) * 2;
    const int p    = mblk * 128 + lrow;
    const int ab   = p >> 12;
    const int aoy  = ((p & 4095) >> 6) << 1;
    const int aox  = (p & 63) << 1;
    const int bgn  = nblk * 128 + lrow;
    const int lsw  = lrow & 7;
    const uint32_t sw0 = (uint32_t)(((s0)     ^ lsw) * 16);
    const uint32_t sw1 = (uint32_t)(((s0 + 1) ^ lsw) * 16);

    auto issue_chunk = [&](int cc, int stg) {
        const int tap = cc >> 1;
        const int kc  = (cc & 1) << 6;                // 0 or 64
        const int dyr = (tap * 11) >> 5;              // tap / 3 (exact 0..8)
        const int iy  = aoy + dyr - 1;
        const int ix  = aox + (tap - dyr * 3) - 1;
        const bool valid = ((unsigned)iy < 128u) && ((unsigned)ix < 128u);
        const uint32_t vs = valid ? 16u : 0u;
        const int cy = valid ? iy : 0, cx = valid ? ix : 0;
        const __half* asrc =
            g_Ah + ((size_t)(((ab << 7) + cy) << 7) + cx) * CIN + kc + s0 * 8;
        const uint32_t stage = sb + (uint32_t)stg * STAGE_BYTES;
        const uint32_t arb = stage + lrow * 128;
        cp_async16z(arb + sw0, asrc,     vs);
        cp_async16z(arb + sw1, asrc + 8, vs);
        const __half* bsrc =
            g_Wh + (size_t)bgn * K_TOTAL + (size_t)tap * 128 + kc + s0 * 8;
        const uint32_t brb = stage + OFF_B + lrow * 128;
        cp_async16(brb + sw0, bsrc);
        cp_async16(brb + sw1, bsrc + 8);
    };

    float acc[2][4][4];
    #pragma unroll
    for (int i = 0; i < 2; ++i)
        #pragma unroll
        for (int j = 0; j < 4; ++j)
            #pragma unroll
            for (int q = 0; q < 4; ++q) acc[i][j][q] = 0.f;

    // ---- ldsm addressing ----
    const int arow_l = wm * 32 + (l & 15);
    const int a_rs   = arow_l & 7;
    const uint32_t a_base0 = sb + arow_l * 128;
    const int brow_l = wn * 32 + ((l >> 4) << 3) + (l & 7);
    const int b_rs   = brow_l & 7;
    const uint32_t b_base0 = sb + OFF_B + brow_l * 128;
    // chunk selectors (invariant): A uses k16*2 + (l>>4), B uses k16*2 + ((l>>3)&1)
    const int a_csel = (l >> 4);
    const int b_csel = ((l >> 3) & 1);

    // ---- prologue: fill 2 stages ----
    issue_chunk(0, 0); cp_commit();
    issue_chunk(1, 1); cp_commit();

    #pragma unroll 1
    for (int c = 0; c < NCHUNK; ++c) {
        const uint32_t soff = (uint32_t)(c % NSTAGE) * STAGE_BYTES;

        cp_wait<1>();
        __syncthreads();           // all warps finished stage (c-1)%NSTAGE

        if (c + 2 < NCHUNK) issue_chunk(c + 2, (c + 2) % NSTAGE);
        cp_commit();

        #pragma unroll
        for (int k16 = 0; k16 < 4; ++k16) {
            const uint32_t a_off = (uint32_t)(((k16 * 2 + a_csel) ^ a_rs) * 16);
            const uint32_t b_off = (uint32_t)(((k16 * 2 + b_csel) ^ b_rs) * 16);
            uint32_t af[2][4], bh[4];
            ldsm_x4(af[0][0], af[0][1], af[0][2], af[0][3], a_base0 + a_off + soff);
            ldsm_x4(af[1][0], af[1][1], af[1][2], af[1][3],
                    a_base0 + 16 * 128 + a_off + soff);
            ldsm_x4(bh[0], bh[1], bh[2], bh[3], b_base0 + b_off + soff);
            #pragma unroll
            for (int mt = 0; mt < 2; ++mt) {
                #pragma unroll
                for (int sub = 0; sub < 2; ++sub)
                    mma16816(acc[mt][sub], af[mt], bh[sub * 2], bh[sub * 2 + 1]);
            }
            ldsm_x4(bh[0], bh[1], bh[2], bh[3], b_base0 + 16 * 128 + b_off + soff);
            #pragma unroll
            for (int mt = 0; mt < 2; ++mt) {
                #pragma unroll
                for (int sub = 0; sub < 2; ++sub)
                    mma16816(acc[mt][2 + sub], af[mt], bh[sub * 2], bh[sub * 2 + 1]);
            }
        }
    }

    // ---- epilogue ----
    const int row_base = mblk * 128 + wm * 32 + (l >> 2);
    const int col_base = nblk * 128 + wn * 32 + (l & 3) * 2;
    #pragma unroll
    for (int mt = 0; mt < 2; ++mt) {
        #pragma unroll
        for (int nt = 0; nt < 4; ++nt) {
            const int r0 = row_base + mt * 16;
            const int cc = col_base + nt * 8;
            float* o0 = out + (size_t)r0 * COUT + cc;
            float* o1 = out + (size_t)(r0 + 8) * COUT + cc;
            *reinterpret_cast<float2*>(o0) = make_float2(acc[mt][nt][0], acc[mt][nt][1]);
            *reinterpret_cast<float2*>(o1) = make_float2(acc[mt][nt][2], acc[mt][nt][3]);
        }
    }
}

// ---------------- launch ----------------
extern "C" void kernel_launch(void* const* d_in, const int* in_sizes, int n_in,
                              void* d_out, int out_size)
{
    const float* feats  = (const float*)d_in[0];
    const float* weight = (const float*)d_in[1];
    const float* alpha  = (const float*)d_in[2];
    float* out = (float*)d_out;

    cudaFuncSetAttribute(conv_mma_kernel,
                         cudaFuncAttributeMaxDynamicSharedMemorySize, SMEM_TOTAL);

    prep_kernel<<<A4_BLOCKS + (K_TOTAL / 32) * (COUT / 32), 256>>>(feats, weight);
    dim3 grid(M_TOTAL / BM, COUT / BN);    // (256, 2)
    conv_mma_kernel<<<grid, NTHREADS, SMEM_TOTAL>>>(alpha, out);
}

// round 12
// speedup vs baseline: 1.0183x; 1.0183x over previous
#include <cuda_runtime.h>
#include <cuda_fp16.h>
#include <cstdint>

// ---------------- problem constants ----------------
#define CIN 128
#define COUT 256
#define NPIX (8 * 128 * 128)
#define M_TOTAL 32768                      // 8 * 64 * 64
#define K_TOTAL 1152                       // 9 * 128
#define FEATS_OUT_ELEMS ((size_t)M_TOTAL * COUT)
#define COORD_OUT_ELEMS ((size_t)M_TOTAL * 3)

// ---------------- GEMM config ----------------
#define BM 128
#define BN 128
#define BK 32
#define NCHUNK 36
#define NSTAGE 6
#define LOOKAHEAD 5
#define NTHREADS 512          // 16 warps: 4 m x 4 n, warp tile 32x32

// smem stage: A 128 rows x 64B, then B 128 rows x 64B
// phys16B(chunk) = (chunk ^ ((row>>1)&3)) * 16
#define OFF_B 8192
#define STAGE_BYTES 16384
#define SMEM_TOTAL (NSTAGE * STAGE_BYTES)   // 98304; 2 CTAs/SM -> 192KB/SM

// ---------------- device scratch ----------------
__device__ __align__(16) __half g_Wh[COUT * K_TOTAL];            // [n][k] fp16
__device__ __align__(16) __half g_Ah[(size_t)NPIX * CIN];        // feats fp16

// ---------------- helpers ----------------
__device__ __forceinline__ uint32_t smem_u32(const void* p) {
    uint32_t a;
    asm("{ .reg .u64 t; cvta.to.shared.u64 t, %1; cvt.u32.u64 %0, t; }" : "=r"(a) : "l"(p));
    return a;
}
__device__ __forceinline__ void cp_async16(uint32_t dst, const void* src) {
    asm volatile("cp.async.cg.shared.global [%0], [%1], 16;" :: "r"(dst), "l"(src) : "memory");
}
__device__ __forceinline__ void cp_async16z(uint32_t dst, const void* src, uint32_t src_size) {
    asm volatile("cp.async.cg.shared.global [%0], [%1], 16, %2;"
                 :: "r"(dst), "l"(src), "r"(src_size) : "memory");
}
__device__ __forceinline__ void cp_commit() {
    asm volatile("cp.async.commit_group;" ::: "memory");
}
template <int N>
__device__ __forceinline__ void cp_wait() {
    asm volatile("cp.async.wait_group %0;" :: "n"(N) : "memory");
}
__device__ __forceinline__ void ldsm_x4(uint32_t& r0, uint32_t& r1, uint32_t& r2, uint32_t& r3,
                                        uint32_t addr) {
    asm volatile("ldmatrix.sync.aligned.m8n8.x4.shared.b16 {%0,%1,%2,%3}, [%4];"
                 : "=r"(r0), "=r"(r1), "=r"(r2), "=r"(r3) : "r"(addr));
}
__device__ __forceinline__ void mma16816(float* c, const uint32_t* a, uint32_t b0, uint32_t b1) {
    asm volatile("mma.sync.aligned.m16n8k16.row.col.f32.f16.f16.f32 "
                 "{%0,%1,%2,%3}, {%4,%5,%6,%7}, {%8,%9}, {%0,%1,%2,%3};"
                 : "+f"(c[0]), "+f"(c[1]), "+f"(c[2]), "+f"(c[3])
                 : "r"(a[0]), "r"(a[1]), "r"(a[2]), "r"(a[3]), "r"(b0), "r"(b1));
}

// ---------------- fused prep: A fp32->fp16 stream + W transpose + coords ----------------
#define A4_TOTAL ((size_t)NPIX * CIN / 4)
#define A4_BLOCKS 16384
#define W_BLOCKS ((K_TOTAL / 32) * (COUT / 32))    // 288
#define C_BLOCKS (M_TOTAL / 256)                   // 128
__global__ __launch_bounds__(256)
void prep_kernel(const float* __restrict__ feats, const float* __restrict__ w,
                 const float* __restrict__ alpha, float* __restrict__ out) {
    __shared__ float tile[32][33];
    if (blockIdx.x < A4_BLOCKS) {
        size_t i4 = (size_t)blockIdx.x * 256 + threadIdx.x;
        float4 v = reinterpret_cast<const float4*>(feats)[i4];
        __half2 h0 = __floats2half2_rn(v.x, v.y);
        __half2 h1 = __floats2half2_rn(v.z, v.w);
        reinterpret_cast<uint2*>(g_Ah)[i4] =
            make_uint2(*reinterpret_cast<uint32_t*>(&h0), *reinterpret_cast<uint32_t*>(&h1));
    } else if (blockIdx.x < A4_BLOCKS + W_BLOCKS) {
        const int bid = blockIdx.x - A4_BLOCKS;
        const int kt = bid % (K_TOTAL / 32);
        const int nt = bid / (K_TOTAL / 32);
        const int ty = threadIdx.x >> 5, tx = threadIdx.x & 31;
        #pragma unroll
        for (int j = 0; j < 4; ++j)
            tile[ty + j * 8][tx] = w[(size_t)(kt * 32 + ty + j * 8) * COUT + nt * 32 + tx];
        __syncthreads();
        #pragma unroll
        for (int j = 0; j < 4; ++j) {
            const int nr = nt * 32 + ty + j * 8;
            const int k  = kt * 32 + tx;
            g_Wh[(size_t)nr * K_TOTAL + k] = __float2half_rn(tile[tx][ty + j * 8]);
        }
    } else {
        const int p = (blockIdx.x - A4_BLOCKS - W_BLOCKS) * 256 + threadIdx.x;
        float* row = out + FEATS_OUT_ELEMS + (size_t)p * 3;
        row[0] = (float)(p >> 12);
        row[1] = (float)((p & 4095) >> 6);
        row[2] = (float)(p & 63);
        if (p == 0)
            out[FEATS_OUT_ELEMS + COORD_OUT_ELEMS] = alpha[0];
    }
}

// ---------------- main GEMM kernel ----------------
__global__ __launch_bounds__(NTHREADS, 2)
void conv_mma_kernel(float* __restrict__ out)
{
    extern __shared__ char smem[];
    const uint32_t sb = smem_u32(smem);
    const int tid = threadIdx.x;
    const int w = tid >> 5, l = tid & 31;
    const int mblk = blockIdx.x, nblk = blockIdx.y;
    const int wm = w & 3, wn = w >> 2;      // 4m x 4n, warp tile 32x32

    // ---- loader geometry: thread -> row tid>>2, 16B seg tid&3
    const int lrow = tid >> 2;
    const int lseg = tid & 3;
    const int p    = mblk * 128 + lrow;
    const int ab   = p >> 12;
    const int aoy  = ((p & 4095) >> 6) << 1;
    const int aox  = (p & 63) << 1;
    const int bgn  = nblk * 128 + lrow;
    const uint32_t csw = (uint32_t)((lseg ^ ((lrow >> 1) & 3)) * 16);

    auto issue_chunk = [&](int cc, int stg) {
        const int tap = cc >> 2, kc = (cc & 3) << 5;
        const int iy = aoy + tap / 3 - 1;
        const int ix = aox + tap % 3 - 1;
        const bool valid = ((unsigned)iy < 128u) && ((unsigned)ix < 128u);
        const uint32_t vs = valid ? 16u : 0u;
        const int cy = valid ? iy : 0, cx = valid ? ix : 0;
        const __half* asrc =
            g_Ah + ((size_t)(((ab << 7) + cy) << 7) + cx) * CIN + kc + lseg * 8;
        const uint32_t stage = sb + (uint32_t)stg * STAGE_BYTES;
        cp_async16z(stage + lrow * 64 + csw, asrc, vs);
        const __half* bsrc =
            g_Wh + (size_t)bgn * K_TOTAL + (size_t)tap * 128 + kc + lseg * 8;
        cp_async16(stage + OFF_B + lrow * 64 + csw, bsrc);
    };

    float acc[2][4][4];
    #pragma unroll
    for (int i = 0; i < 2; ++i)
        #pragma unroll
        for (int j = 0; j < 4; ++j)
            #pragma unroll
            for (int q = 0; q < 4; ++q) acc[i][j][q] = 0.f;

    // ---- ldsm addressing (frugal) ----
    const int arow_l = wm * 32 + (l & 15);
    const int a_rs   = (arow_l >> 1) & 3;
    const uint32_t a_base0 = sb + arow_l * 64;
    const int brow_l = wn * 32 + ((l >> 4) << 3) + (l & 7);
    const int b_rs   = (brow_l >> 1) & 3;
    const uint32_t b_base0 = sb + OFF_B + brow_l * 64;

    // ---- prologue: fill LOOKAHEAD stages ----
    #pragma unroll
    for (int s = 0; s < LOOKAHEAD; ++s) { issue_chunk(s, s); cp_commit(); }

    #pragma unroll 1
    for (int c = 0; c < NCHUNK; ++c) {
        const uint32_t soff = (uint32_t)(c % NSTAGE) * STAGE_BYTES;

        cp_wait<LOOKAHEAD - 1>();
        __syncthreads();           // all warps finished stage (c-1)%NSTAGE

        if (c + LOOKAHEAD < NCHUNK) issue_chunk(c + LOOKAHEAD, (c + LOOKAHEAD) % NSTAGE);
        cp_commit();               // unconditional: keeps group indices advancing

        #pragma unroll
        for (int k16 = 0; k16 < 2; ++k16) {
            const uint32_t a_off = (uint32_t)(((k16 * 2 + (l >> 4)) ^ a_rs) * 16);
            const uint32_t b_off = (uint32_t)(((k16 * 2 + ((l >> 3) & 1)) ^ b_rs) * 16);
            uint32_t af[2][4], bh[4];
            ldsm_x4(af[0][0], af[0][1], af[0][2], af[0][3], a_base0 + a_off + soff);
            ldsm_x4(af[1][0], af[1][1], af[1][2], af[1][3],
                    a_base0 + 16 * 64 + a_off + soff);
            ldsm_x4(bh[0], bh[1], bh[2], bh[3], b_base0 + b_off + soff);
            #pragma unroll
            for (int mt = 0; mt < 2; ++mt) {
                #pragma unroll
                for (int sub = 0; sub < 2; ++sub)
                    mma16816(acc[mt][sub], af[mt], bh[sub * 2], bh[sub * 2 + 1]);
            }
            ldsm_x4(bh[0], bh[1], bh[2], bh[3], b_base0 + 16 * 64 + b_off + soff);
            #pragma unroll
            for (int mt = 0; mt < 2; ++mt) {
                #pragma unroll
                for (int sub = 0; sub < 2; ++sub)
                    mma16816(acc[mt][2 + sub], af[mt], bh[sub * 2], bh[sub * 2 + 1]);
            }
        }
    }

    // ---- epilogue ----
    const int row_base = mblk * 128 + wm * 32 + (l >> 2);
    const int col_base = nblk * 128 + wn * 32 + (l & 3) * 2;
    #pragma unroll
    for (int mt = 0; mt < 2; ++mt) {
        #pragma unroll
        for (int nt = 0; nt < 4; ++nt) {
            const int r0 = row_base + mt * 16;
            const int cc = col_base + nt * 8;
            float* o0 = out + (size_t)r0 * COUT + cc;
            float* o1 = out + (size_t)(r0 + 8) * COUT + cc;
            *reinterpret_cast<float2*>(o0) = make_float2(acc[mt][nt][0], acc[mt][nt][1]);
            *reinterpret_cast<float2*>(o1) = make_float2(acc[mt][nt][2], acc[mt][nt][3]);
        }
    }
}

// ---------------- launch ----------------
extern "C" void kernel_launch(void* const* d_in, const int* in_sizes, int n_in,
                              void* d_out, int out_size)
{
    const float* feats  = (const float*)d_in[0];
    const float* weight = (const float*)d_in[1];
    const float* alpha  = (const float*)d_in[2];
    float* out = (float*)d_out;

    cudaFuncSetAttribute(conv_mma_kernel,
                         cudaFuncAttributeMaxDynamicSharedMemorySize, SMEM_TOTAL);

    prep_kernel<<<A4_BLOCKS + W_BLOCKS + C_BLOCKS, 256>>>(feats, weight, alpha, out);
    dim3 grid(M_TOTAL / BM, COUT / BN);    // (256, 2)
    conv_mma_kernel<<<grid, NTHREADS, SMEM_TOTAL>>>(out);
}

// round 13
// speedup vs baseline: 1.1108x; 1.0908x over previous
#include <cuda_runtime.h>
#include <cuda_fp16.h>
#include <cstdint>

// ---------------- problem constants ----------------
#define CIN 128
#define COUT 256
#define NPIX (8 * 128 * 128)
#define M_TOTAL 32768                      // 8 * 64 * 64
#define K_TOTAL 1152                       // 9 * 128
#define FEATS_OUT_ELEMS ((size_t)M_TOTAL * COUT)
#define COORD_OUT_ELEMS ((size_t)M_TOTAL * 3)

// ---------------- GEMM config ----------------
#define BM 128
#define BN 128
#define NSTAGE 4
#define NTHREADS 512          // 16 warps: 4 m x 4 n, warp tile 32x32

// smem stage: A 128 rows x 64B, then B 128 rows x 64B
// phys16B(chunk) = (chunk ^ ((row>>1)&3)) * 16
#define OFF_B 8192
#define STAGE_BYTES 16384u
#define SMEM_TOTAL (NSTAGE * STAGE_BYTES)   // 65536; 2 CTAs/SM

// ---------------- device scratch ----------------
__device__ __align__(16) __half g_Wh[COUT * K_TOTAL];            // [n][k] fp16
__device__ __align__(16) __half g_Ah[(size_t)NPIX * CIN];        // feats fp16

// ---------------- helpers ----------------
__device__ __forceinline__ uint32_t smem_u32(const void* p) {
    uint32_t a;
    asm("{ .reg .u64 t; cvta.to.shared.u64 t, %1; cvt.u32.u64 %0, t; }" : "=r"(a) : "l"(p));
    return a;
}
__device__ __forceinline__ void cp_async16(uint32_t dst, const void* src) {
    asm volatile("cp.async.cg.shared.global [%0], [%1], 16;" :: "r"(dst), "l"(src) : "memory");
}
__device__ __forceinline__ void cp_async16z(uint32_t dst, const void* src, uint32_t src_size) {
    asm volatile("cp.async.cg.shared.global [%0], [%1], 16, %2;"
                 :: "r"(dst), "l"(src), "r"(src_size) : "memory");
}
__device__ __forceinline__ void cp_commit() {
    asm volatile("cp.async.commit_group;" ::: "memory");
}
template <int N>
__device__ __forceinline__ void cp_wait() {
    asm volatile("cp.async.wait_group %0;" :: "n"(N) : "memory");
}
__device__ __forceinline__ void ldsm_x4(uint32_t& r0, uint32_t& r1, uint32_t& r2, uint32_t& r3,
                                        uint32_t addr) {
    asm volatile("ldmatrix.sync.aligned.m8n8.x4.shared.b16 {%0,%1,%2,%3}, [%4];"
                 : "=r"(r0), "=r"(r1), "=r"(r2), "=r"(r3) : "r"(addr));
}
__device__ __forceinline__ void mma16816(float* c, const uint32_t* a, uint32_t b0, uint32_t b1) {
    asm volatile("mma.sync.aligned.m16n8k16.row.col.f32.f16.f16.f32 "
                 "{%0,%1,%2,%3}, {%4,%5,%6,%7}, {%8,%9}, {%0,%1,%2,%3};"
                 : "+f"(c[0]), "+f"(c[1]), "+f"(c[2]), "+f"(c[3])
                 : "r"(a[0]), "r"(a[1]), "r"(a[2]), "r"(a[3]), "r"(b0), "r"(b1));
}

// ---------------- fused prep: A fp32->fp16 stream + W transpose + coords ----------------
#define A4_BLOCKS 16384
#define W_BLOCKS ((K_TOTAL / 32) * (COUT / 32))    // 288
#define C_BLOCKS (M_TOTAL / 256)                   // 128
__global__ __launch_bounds__(256)
void prep_kernel(const float* __restrict__ feats, const float* __restrict__ w,
                 const float* __restrict__ alpha, float* __restrict__ out) {
    __shared__ float tile[32][33];
    if (blockIdx.x < A4_BLOCKS) {
        size_t i4 = (size_t)blockIdx.x * 256 + threadIdx.x;
        float4 v = reinterpret_cast<const float4*>(feats)[i4];
        __half2 h0 = __floats2half2_rn(v.x, v.y);
        __half2 h1 = __floats2half2_rn(v.z, v.w);
        reinterpret_cast<uint2*>(g_Ah)[i4] =
            make_uint2(*reinterpret_cast<uint32_t*>(&h0), *reinterpret_cast<uint32_t*>(&h1));
    } else if (blockIdx.x < A4_BLOCKS + W_BLOCKS) {
        const int bid = blockIdx.x - A4_BLOCKS;
        const int kt = bid % (K_TOTAL / 32);
        const int nt = bid / (K_TOTAL / 32);
        const int ty = threadIdx.x >> 5, tx = threadIdx.x & 31;
        #pragma unroll
        for (int j = 0; j < 4; ++j)
            tile[ty + j * 8][tx] = w[(size_t)(kt * 32 + ty + j * 8) * COUT + nt * 32 + tx];
        __syncthreads();
        #pragma unroll
        for (int j = 0; j < 4; ++j) {
            const int nr = nt * 32 + ty + j * 8;
            const int k  = kt * 32 + tx;
            g_Wh[(size_t)nr * K_TOTAL + k] = __float2half_rn(tile[tx][ty + j * 8]);
        }
    } else {
        const int p = (blockIdx.x - A4_BLOCKS - W_BLOCKS) * 256 + threadIdx.x;
        float* row = out + FEATS_OUT_ELEMS + (size_t)p * 3;
        row[0] = (float)(p >> 12);
        row[1] = (float)((p & 4095) >> 6);
        row[2] = (float)(p & 63);
        if (p == 0)
            out[FEATS_OUT_ELEMS + COORD_OUT_ELEMS] = alpha[0];
    }
}

// ---------------- main GEMM kernel ----------------
__global__ __launch_bounds__(NTHREADS, 2)
void conv_mma_kernel(float* __restrict__ out)
{
    extern __shared__ char smem[];
    const uint32_t sb = smem_u32(smem);
    const int tid = threadIdx.x;
    const int w = tid >> 5, l = tid & 31;
    const int mblk = blockIdx.x, nblk = blockIdx.y;
    const int wm = w & 3, wn = w >> 2;      // 4m x 4n, warp tile 32x32

    // ---- loader geometry: thread -> row tid>>2, 16B seg tid&3
    const int lrow = tid >> 2;
    const int lseg = tid & 3;
    const int p    = mblk * 128 + lrow;
    const int ab   = p >> 12;
    const int aoy  = ((p & 4095) >> 6) << 1;
    const int aox  = (p & 63) << 1;
    const int bgn  = nblk * 128 + lrow;
    const uint32_t a_dst = sb + lrow * 64 + (uint32_t)((lseg ^ ((lrow >> 1) & 3)) * 16);
    const uint32_t b_dst = a_dst + OFF_B;

    // compute A source base + validity for a tap (once per 4 chunks)
    auto tap_a = [&](int tap, const __half*& abase, uint32_t& vs) {
        const int dyr = (tap * 11) >> 5;             // tap / 3, exact for 0..8
        const int iy = aoy + dyr - 1;
        const int ix = aox + (tap - dyr * 3) - 1;
        const bool valid = ((unsigned)iy < 128u) && ((unsigned)ix < 128u);
        vs = valid ? 16u : 0u;
        const int cy = valid ? iy : 0, cx = valid ? ix : 0;
        abase = g_Ah + ((size_t)(((ab << 7) + cy) << 7) + cx) * CIN + lseg * 8;
    };
    // issue one chunk's loads: kc + stage offset are compile-time after unroll
    auto issue = [&](const __half* abase, uint32_t vs, const __half* bbase,
                     int kc, uint32_t soff) {
        cp_async16z(a_dst + soff, abase + kc, vs);
        cp_async16(b_dst + soff, bbase + kc);
    };

    float acc[2][4][4];
    #pragma unroll
    for (int i = 0; i < 2; ++i)
        #pragma unroll
        for (int j = 0; j < 4; ++j)
            #pragma unroll
            for (int q = 0; q < 4; ++q) acc[i][j][q] = 0.f;

    // ---- ldsm addressing (loop-invariant offsets) ----
    const int arow_l = wm * 32 + (l & 15);
    const int a_rs   = (arow_l >> 1) & 3;
    const uint32_t a_base0 = sb + arow_l * 64;
    const int brow_l = wn * 32 + ((l >> 4) << 3) + (l & 7);
    const int b_rs   = (brow_l >> 1) & 3;
    const uint32_t b_base0 = sb + OFF_B + brow_l * 64;
    uint32_t a_off[2], b_off[2];
    #pragma unroll
    for (int k16 = 0; k16 < 2; ++k16) {
        a_off[k16] = (uint32_t)(((k16 * 2 + (l >> 4)) ^ a_rs) * 16);
        b_off[k16] = (uint32_t)(((k16 * 2 + ((l >> 3) & 1)) ^ b_rs) * 16);
    }

    // ---- prologue: tap 0, chunks 0..2 into stages 0..2 ----
    const __half* acur; uint32_t vcur;
    tap_a(0, acur, vcur);
    const __half* bcur = g_Wh + (size_t)bgn * K_TOTAL + lseg * 8;
    issue(acur, vcur, bcur, 0,  0);                cp_commit();
    issue(acur, vcur, bcur, 32, STAGE_BYTES);      cp_commit();
    issue(acur, vcur, bcur, 64, 2 * STAGE_BYTES);  cp_commit();

    // ---- main loop: 9 taps x 4 chunks; stage = j (compile-time) ----
    #pragma unroll 1
    for (int t = 0; t < 9; ++t) {
        const __half* anxt = acur; uint32_t vnxt = 0;
        const __half* bnxt = bcur + 128;
        if (t < 8) tap_a(t + 1, anxt, vnxt);

        #pragma unroll
        for (int j = 0; j < 4; ++j) {
            cp_wait<2>();
            __syncthreads();       // all warps finished the stage being refilled

            // prefetch chunk (4t+j+3) into stage (j+3)&3
            if (j == 0)            issue(acur, vcur, bcur, 96, 3 * STAGE_BYTES);
            else if (t < 8)        issue(anxt, vnxt, bnxt, (j - 1) * 32,
                                         (uint32_t)(((j + 3) & 3)) * STAGE_BYTES);
            cp_commit();           // unconditional: keeps group indices advancing

            const uint32_t soff = (uint32_t)j * STAGE_BYTES;   // immediate
            #pragma unroll
            for (int k16 = 0; k16 < 2; ++k16) {
                uint32_t af[2][4], bh[4];
                ldsm_x4(af[0][0], af[0][1], af[0][2], af[0][3],
                        a_base0 + a_off[k16] + soff);
                ldsm_x4(af[1][0], af[1][1], af[1][2], af[1][3],
                        a_base0 + 16 * 64 + a_off[k16] + soff);
                ldsm_x4(bh[0], bh[1], bh[2], bh[3], b_base0 + b_off[k16] + soff);
                #pragma unroll
                for (int mt = 0; mt < 2; ++mt)
                    #pragma unroll
                    for (int sub = 0; sub < 2; ++sub)
                        mma16816(acc[mt][sub], af[mt], bh[sub * 2], bh[sub * 2 + 1]);
                ldsm_x4(bh[0], bh[1], bh[2], bh[3],
                        b_base0 + 16 * 64 + b_off[k16] + soff);
                #pragma unroll
                for (int mt = 0; mt < 2; ++mt)
                    #pragma unroll
                    for (int sub = 0; sub < 2; ++sub)
                        mma16816(acc[mt][2 + sub], af[mt], bh[sub * 2], bh[sub * 2 + 1]);
            }
        }
        acur = anxt; vcur = vnxt; bcur = bnxt;
    }

    // ---- epilogue ----
    const int row_base = mblk * 128 + wm * 32 + (l >> 2);
    const int col_base = nblk * 128 + wn * 32 + (l & 3) * 2;
    #pragma unroll
    for (int mt = 0; mt < 2; ++mt) {
        #pragma unroll
        for (int nt = 0; nt < 4; ++nt) {
            const int r0 = row_base + mt * 16;
            const int cc = col_base + nt * 8;
            float* o0 = out + (size_t)r0 * COUT + cc;
            float* o1 = out + (size_t)(r0 + 8) * COUT + cc;
            *reinterpret_cast<float2*>(o0) = make_float2(acc[mt][nt][0], acc[mt][nt][1]);
            *reinterpret_cast<float2*>(o1) = make_float2(acc[mt][nt][2], acc[mt][nt][3]);
        }
    }
}

// ---------------- launch ----------------
extern "C" void kernel_launch(void* const* d_in, const int* in_sizes, int n_in,
                              void* d_out, int out_size)
{
    const float* feats  = (const float*)d_in[0];
    const float* weight = (const float*)d_in[1];
    const float* alpha  = (const float*)d_in[2];
    float* out = (float*)d_out;

    cudaFuncSetAttribute(conv_mma_kernel,
                         cudaFuncAttributeMaxDynamicSharedMemorySize, SMEM_TOTAL);

    prep_kernel<<<A4_BLOCKS + W_BLOCKS + C_BLOCKS, 256>>>(feats, weight, alpha, out);
    dim3 grid(M_TOTAL / BM, COUT / BN);    // (256, 2)
    conv_mma_kernel<<<grid, NTHREADS, SMEM_TOTAL>>>(out);
}

// round 14
// speedup vs baseline: 1.1133x; 1.0023x over previous
#include <cuda_runtime.h>
#include <cuda_fp16.h>
#include <cstdint>

// ---------------- problem constants ----------------
#define CIN 128
#define COUT 256
#define NPIX (8 * 128 * 128)
#define M_TOTAL 32768                      // 8 * 64 * 64
#define K_TOTAL 1152                       // 9 * 128
#define FEATS_OUT_ELEMS ((size_t)M_TOTAL * COUT)
#define COORD_OUT_ELEMS ((size_t)M_TOTAL * 3)

// ---------------- GEMM config ----------------
#define BM 128
#define BN 128
#define NSTAGE 4
#define NTHREADS 512          // 16 warps: 4 m x 4 n, warp tile 32x32

// smem stage: A 128 rows x 64B, then B 128 rows x 64B
// phys16B(chunk) = (chunk ^ ((row>>1)&3)) * 16
#define OFF_B 8192
#define STAGE_BYTES 16384u
#define SMEM_TOTAL (NSTAGE * STAGE_BYTES)   // 65536; 2 CTAs/SM

// ---------------- device scratch ----------------
__device__ __align__(16) __half g_Wh[COUT * K_TOTAL];            // [n][k] fp16
__device__ __align__(16) __half g_Ah[(size_t)NPIX * CIN];        // feats fp16

// ---------------- helpers ----------------
__device__ __forceinline__ uint32_t smem_u32(const void* p) {
    uint32_t a;
    asm("{ .reg .u64 t; cvta.to.shared.u64 t, %1; cvt.u32.u64 %0, t; }" : "=r"(a) : "l"(p));
    return a;
}
__device__ __forceinline__ void cp_async16(uint32_t dst, const void* src) {
    asm volatile("cp.async.cg.shared.global [%0], [%1], 16;" :: "r"(dst), "l"(src) : "memory");
}
__device__ __forceinline__ void cp_async16z(uint32_t dst, const void* src, uint32_t src_size) {
    asm volatile("cp.async.cg.shared.global [%0], [%1], 16, %2;"
                 :: "r"(dst), "l"(src), "r"(src_size) : "memory");
}
__device__ __forceinline__ void cp_commit() {
    asm volatile("cp.async.commit_group;" ::: "memory");
}
template <int N>
__device__ __forceinline__ void cp_wait() {
    asm volatile("cp.async.wait_group %0;" :: "n"(N) : "memory");
}
__device__ __forceinline__ void ldsm_x4(uint32_t& r0, uint32_t& r1, uint32_t& r2, uint32_t& r3,
                                        uint32_t addr) {
    asm volatile("ldmatrix.sync.aligned.m8n8.x4.shared.b16 {%0,%1,%2,%3}, [%4];"
                 : "=r"(r0), "=r"(r1), "=r"(r2), "=r"(r3) : "r"(addr));
}
__device__ __forceinline__ void mma16816(float* c, const uint32_t* a, uint32_t b0, uint32_t b1) {
    asm volatile("mma.sync.aligned.m16n8k16.row.col.f32.f16.f16.f32 "
                 "{%0,%1,%2,%3}, {%4,%5,%6,%7}, {%8,%9}, {%0,%1,%2,%3};"
                 : "+f"(c[0]), "+f"(c[1]), "+f"(c[2]), "+f"(c[3])
                 : "r"(a[0]), "r"(a[1]), "r"(a[2]), "r"(a[3]), "r"(b0), "r"(b1));
}

// ---------------- fused prep: A fp32->fp16 stream + W transpose + coords ----------------
#define A4_BLOCKS 16384
#define W_BLOCKS ((K_TOTAL / 32) * (COUT / 32))    // 288
#define C_BLOCKS (M_TOTAL / 256)                   // 128
__global__ __launch_bounds__(256)
void prep_kernel(const float* __restrict__ feats, const float* __restrict__ w,
                 const float* __restrict__ alpha, float* __restrict__ out) {
    __shared__ float tile[32][33];
    if (blockIdx.x < A4_BLOCKS) {
        size_t i4 = (size_t)blockIdx.x * 256 + threadIdx.x;
        float4 v = reinterpret_cast<const float4*>(feats)[i4];
        __half2 h0 = __floats2half2_rn(v.x, v.y);
        __half2 h1 = __floats2half2_rn(v.z, v.w);
        reinterpret_cast<uint2*>(g_Ah)[i4] =
            make_uint2(*reinterpret_cast<uint32_t*>(&h0), *reinterpret_cast<uint32_t*>(&h1));
    } else if (blockIdx.x < A4_BLOCKS + W_BLOCKS) {
        const int bid = blockIdx.x - A4_BLOCKS;
        const int kt = bid % (K_TOTAL / 32);
        const int nt = bid / (K_TOTAL / 32);
        const int ty = threadIdx.x >> 5, tx = threadIdx.x & 31;
        #pragma unroll
        for (int j = 0; j < 4; ++j)
            tile[ty + j * 8][tx] = w[(size_t)(kt * 32 + ty + j * 8) * COUT + nt * 32 + tx];
        __syncthreads();
        #pragma unroll
        for (int j = 0; j < 4; ++j) {
            const int nr = nt * 32 + ty + j * 8;
            const int k  = kt * 32 + tx;
            g_Wh[(size_t)nr * K_TOTAL + k] = __float2half_rn(tile[tx][ty + j * 8]);
        }
    } else {
        const int p = (blockIdx.x - A4_BLOCKS - W_BLOCKS) * 256 + threadIdx.x;
        float* row = out + FEATS_OUT_ELEMS + (size_t)p * 3;
        row[0] = (float)(p >> 12);
        row[1] = (float)((p & 4095) >> 6);
        row[2] = (float)(p & 63);
        if (p == 0)
            out[FEATS_OUT_ELEMS + COORD_OUT_ELEMS] = alpha[0];
    }
}

// ---------------- main GEMM kernel ----------------
__global__ __launch_bounds__(NTHREADS, 2)
void conv_mma_kernel(float* __restrict__ out)
{
    extern __shared__ char smem[];
    const uint32_t sb = smem_u32(smem);
    const int tid = threadIdx.x;
    const int w = tid >> 5, l = tid & 31;
    const int mblk = blockIdx.x, nblk = blockIdx.y;
    const int wm = w & 3, wn = w >> 2;      // 4m x 4n, warp tile 32x32

    // ---- loader geometry: thread -> row tid>>2, 16B seg tid&3
    const int lrow = tid >> 2;
    const int lseg = tid & 3;
    const int p    = mblk * 128 + lrow;
    const int ab   = p >> 12;
    const int aoy  = ((p & 4095) >> 6) << 1;
    const int aox  = (p & 63) << 1;
    const int bgn  = nblk * 128 + lrow;
    const uint32_t a_dst = sb + lrow * 64 + (uint32_t)((lseg ^ ((lrow >> 1) & 3)) * 16);
    const uint32_t b_dst = a_dst + OFF_B;

    // compute A source base + validity for a tap (once per 4 chunks)
    auto tap_a = [&](int tap, const __half*& abase, uint32_t& vs) {
        const int dyr = (tap * 11) >> 5;             // tap / 3, exact for 0..8
        const int iy = aoy + dyr - 1;
        const int ix = aox + (tap - dyr * 3) - 1;
        const bool valid = ((unsigned)iy < 128u) && ((unsigned)ix < 128u);
        vs = valid ? 16u : 0u;
        const int cy = valid ? iy : 0, cx = valid ? ix : 0;
        abase = g_Ah + ((size_t)(((ab << 7) + cy) << 7) + cx) * CIN + lseg * 8;
    };
    auto issue = [&](const __half* abase, uint32_t vs, const __half* bbase,
                     int kc, uint32_t soff) {
        cp_async16z(a_dst + soff, abase + kc, vs);
        cp_async16(b_dst + soff, bbase + kc);
    };

    float acc[2][4][4];
    #pragma unroll
    for (int i = 0; i < 2; ++i)
        #pragma unroll
        for (int j = 0; j < 4; ++j)
            #pragma unroll
            for (int q = 0; q < 4; ++q) acc[i][j][q] = 0.f;

    // ---- ldsm addressing (loop-invariant offsets) ----
    const int arow_l = wm * 32 + (l & 15);
    const int a_rs   = (arow_l >> 1) & 3;
    const uint32_t a_base0 = sb + arow_l * 64;
    const int brow_l = wn * 32 + ((l >> 4) << 3) + (l & 7);
    const int b_rs   = (brow_l >> 1) & 3;
    const uint32_t b_base0 = sb + OFF_B + brow_l * 64;
    uint32_t a_off[2], b_off[2];
    #pragma unroll
    for (int k16 = 0; k16 < 2; ++k16) {
        a_off[k16] = (uint32_t)(((k16 * 2 + (l >> 4)) ^ a_rs) * 16);
        b_off[k16] = (uint32_t)(((k16 * 2 + ((l >> 3) & 1)) ^ b_rs) * 16);
    }

    // ---- prologue: tap 0, chunks 0..2 into stages 0..2 ----
    const __half* acur; uint32_t vcur;
    tap_a(0, acur, vcur);
    const __half* bcur = g_Wh + (size_t)bgn * K_TOTAL + lseg * 8;
    issue(acur, vcur, bcur, 0,  0);                cp_commit();
    issue(acur, vcur, bcur, 32, STAGE_BYTES);      cp_commit();
    issue(acur, vcur, bcur, 64, 2 * STAGE_BYTES);  cp_commit();

    // ---- main loop: 9 taps x 4 chunks; stage = j (compile-time) ----
    #pragma unroll 1
    for (int t = 0; t < 9; ++t) {
        const __half* anxt = acur; uint32_t vnxt = 0;
        const __half* bnxt = bcur + 128;
        if (t < 8) tap_a(t + 1, anxt, vnxt);

        #pragma unroll
        for (int j = 0; j < 4; ++j) {
            cp_wait<2>();
            __syncthreads();       // all warps finished the stage being refilled

            // prefetch chunk (4t+j+3) into stage (j+3)&3
            if (j == 0)            issue(acur, vcur, bcur, 96, 3 * STAGE_BYTES);
            else if (t < 8)        issue(anxt, vnxt, bnxt, (j - 1) * 32,
                                         (uint32_t)(((j + 3) & 3)) * STAGE_BYTES);
            cp_commit();           // unconditional: keeps group indices advancing

            const uint32_t soff = (uint32_t)j * STAGE_BYTES;   // immediate
            #pragma unroll
            for (int k16 = 0; k16 < 2; ++k16) {
                // all four ldsm issued back-to-back: no WAR serialization,
                // ptxas can overlap their latency with the mma stream
                uint32_t af[2][4], bh0[4], bh1[4];
                ldsm_x4(af[0][0], af[0][1], af[0][2], af[0][3],
                        a_base0 + a_off[k16] + soff);
                ldsm_x4(af[1][0], af[1][1], af[1][2], af[1][3],
                        a_base0 + 16 * 64 + a_off[k16] + soff);
                ldsm_x4(bh0[0], bh0[1], bh0[2], bh0[3],
                        b_base0 + b_off[k16] + soff);
                ldsm_x4(bh1[0], bh1[1], bh1[2], bh1[3],
                        b_base0 + 16 * 64 + b_off[k16] + soff);
                #pragma unroll
                for (int mt = 0; mt < 2; ++mt)
                    #pragma unroll
                    for (int sub = 0; sub < 2; ++sub)
                        mma16816(acc[mt][sub], af[mt], bh0[sub * 2], bh0[sub * 2 + 1]);
                #pragma unroll
                for (int mt = 0; mt < 2; ++mt)
                    #pragma unroll
                    for (int sub = 0; sub < 2; ++sub)
                        mma16816(acc[mt][2 + sub], af[mt], bh1[sub * 2], bh1[sub * 2 + 1]);
            }
        }
        acur = anxt; vcur = vnxt; bcur = bnxt;
    }

    // ---- epilogue ----
    const int row_base = mblk * 128 + wm * 32 + (l >> 2);
    const int col_base = nblk * 128 + wn * 32 + (l & 3) * 2;
    #pragma unroll
    for (int mt = 0; mt < 2; ++mt) {
        #pragma unroll
        for (int nt = 0; nt < 4; ++nt) {
            const int r0 = row_base + mt * 16;
            const int cc = col_base + nt * 8;
            float* o0 = out + (size_t)r0 * COUT + cc;
            float* o1 = out + (size_t)(r0 + 8) * COUT + cc;
            *reinterpret_cast<float2*>(o0) = make_float2(acc[mt][nt][0], acc[mt][nt][1]);
            *reinterpret_cast<float2*>(o1) = make_float2(acc[mt][nt][2], acc[mt][nt][3]);
        }
    }
}

// ---------------- launch ----------------
extern "C" void kernel_launch(void* const* d_in, const int* in_sizes, int n_in,
                              void* d_out, int out_size)
{
    const float* feats  = (const float*)d_in[0];
    const float* weight = (const float*)d_in[1];
    const float* alpha  = (const float*)d_in[2];
    float* out = (float*)d_out;

    cudaFuncSetAttribute(conv_mma_kernel,
                         cudaFuncAttributeMaxDynamicSharedMemorySize, SMEM_TOTAL);

    prep_kernel<<<A4_BLOCKS + W_BLOCKS + C_BLOCKS, 256>>>(feats, weight, alpha, out);
    dim3 grid(M_TOTAL / BM, COUT / BN);    // (256, 2)
    conv_mma_kernel<<<grid, NTHREADS, SMEM_TOTAL>>>(out);
}

// round 15
// speedup vs baseline: 1.1230x; 1.0088x over previous
#include <cuda_runtime.h>
#include <cuda_fp16.h>
#include <cstdint>

// ---------------- problem constants ----------------
#define CIN 128
#define COUT 256
#define NPIX (8 * 128 * 128)
#define M_TOTAL 32768                      // 8 * 64 * 64
#define K_TOTAL 1152                       // 9 * 128
#define FEATS_OUT_ELEMS ((size_t)M_TOTAL * COUT)
#define COORD_OUT_ELEMS ((size_t)M_TOTAL * 3)

// ---------------- GEMM config ----------------
#define BM 128
#define BN 128
#define NSTAGE 6
#define NTHREADS 512          // 16 warps: 4 m x 4 n, warp tile 32x32

// smem stage: A 128 rows x 64B, then B 128 rows x 64B
// phys16B(chunk) = (chunk ^ ((row>>1)&3)) * 16
#define OFF_B 8192
#define STAGE_BYTES 16384u
#define SMEM_TOTAL (NSTAGE * STAGE_BYTES)   // 98304; 2 CTAs/SM -> 192KB/SM

// ---------------- device scratch ----------------
__device__ __align__(16) __half g_Wh[COUT * K_TOTAL];            // [n][k] fp16
__device__ __align__(16) __half g_Ah[(size_t)NPIX * CIN];        // feats fp16

// ---------------- helpers ----------------
__device__ __forceinline__ uint32_t smem_u32(const void* p) {
    uint32_t a;
    asm("{ .reg .u64 t; cvta.to.shared.u64 t, %1; cvt.u32.u64 %0, t; }" : "=r"(a) : "l"(p));
    return a;
}
__device__ __forceinline__ void cp_async16(uint32_t dst, const void* src) {
    asm volatile("cp.async.cg.shared.global [%0], [%1], 16;" :: "r"(dst), "l"(src) : "memory");
}
__device__ __forceinline__ void cp_async16z(uint32_t dst, const void* src, uint32_t src_size) {
    asm volatile("cp.async.cg.shared.global [%0], [%1], 16, %2;"
                 :: "r"(dst), "l"(src), "r"(src_size) : "memory");
}
__device__ __forceinline__ void cp_commit() {
    asm volatile("cp.async.commit_group;" ::: "memory");
}
template <int N>
__device__ __forceinline__ void cp_wait() {
    asm volatile("cp.async.wait_group %0;" :: "n"(N) : "memory");
}
__device__ __forceinline__ void ldsm_x4(uint32_t& r0, uint32_t& r1, uint32_t& r2, uint32_t& r3,
                                        uint32_t addr) {
    asm volatile("ldmatrix.sync.aligned.m8n8.x4.shared.b16 {%0,%1,%2,%3}, [%4];"
                 : "=r"(r0), "=r"(r1), "=r"(r2), "=r"(r3) : "r"(addr));
}
__device__ __forceinline__ void mma16816(float* c, const uint32_t* a, uint32_t b0, uint32_t b1) {
    asm volatile("mma.sync.aligned.m16n8k16.row.col.f32.f16.f16.f32 "
                 "{%0,%1,%2,%3}, {%4,%5,%6,%7}, {%8,%9}, {%0,%1,%2,%3};"
                 : "+f"(c[0]), "+f"(c[1]), "+f"(c[2]), "+f"(c[3])
                 : "r"(a[0]), "r"(a[1]), "r"(a[2]), "r"(a[3]), "r"(b0), "r"(b1));
}

// ---------------- fused prep: A fp32->fp16 stream + W transpose + coords ----------------
#define A4_BLOCKS 16384
#define W_BLOCKS ((K_TOTAL / 32) * (COUT / 32))    // 288
#define C_BLOCKS (M_TOTAL / 256)                   // 128
__global__ __launch_bounds__(256)
void prep_kernel(const float* __restrict__ feats, const float* __restrict__ w,
                 const float* __restrict__ alpha, float* __restrict__ out) {
    __shared__ float tile[32][33];
    if (blockIdx.x < A4_BLOCKS) {
        size_t i4 = (size_t)blockIdx.x * 256 + threadIdx.x;
        float4 v = reinterpret_cast<const float4*>(feats)[i4];
        __half2 h0 = __floats2half2_rn(v.x, v.y);
        __half2 h1 = __floats2half2_rn(v.z, v.w);
        reinterpret_cast<uint2*>(g_Ah)[i4] =
            make_uint2(*reinterpret_cast<uint32_t*>(&h0), *reinterpret_cast<uint32_t*>(&h1));
    } else if (blockIdx.x < A4_BLOCKS + W_BLOCKS) {
        const int bid = blockIdx.x - A4_BLOCKS;
        const int kt = bid % (K_TOTAL / 32);
        const int nt = bid / (K_TOTAL / 32);
        const int ty = threadIdx.x >> 5, tx = threadIdx.x & 31;
        #pragma unroll
        for (int j = 0; j < 4; ++j)
            tile[ty + j * 8][tx] = w[(size_t)(kt * 32 + ty + j * 8) * COUT + nt * 32 + tx];
        __syncthreads();
        #pragma unroll
        for (int j = 0; j < 4; ++j) {
            const int nr = nt * 32 + ty + j * 8;
            const int k  = kt * 32 + tx;
            g_Wh[(size_t)nr * K_TOTAL + k] = __float2half_rn(tile[tx][ty + j * 8]);
        }
    } else {
        const int p = (blockIdx.x - A4_BLOCKS - W_BLOCKS) * 256 + threadIdx.x;
        float* row = out + FEATS_OUT_ELEMS + (size_t)p * 3;
        row[0] = (float)(p >> 12);
        row[1] = (float)((p & 4095) >> 6);
        row[2] = (float)(p & 63);
        if (p == 0)
            out[FEATS_OUT_ELEMS + COORD_OUT_ELEMS] = alpha[0];
    }
}

// ---------------- main GEMM kernel ----------------
__global__ __launch_bounds__(NTHREADS, 2)
void conv_mma_kernel(float* __restrict__ out)
{
    extern __shared__ char smem[];
    const uint32_t sb = smem_u32(smem);
    const int tid = threadIdx.x;
    const int w = tid >> 5, l = tid & 31;
    const int mblk = blockIdx.x, nblk = blockIdx.y;
    const int wm = w & 3, wn = w >> 2;      // 4m x 4n, warp tile 32x32

    // ---- loader geometry: thread -> row tid>>2, 16B seg tid&3
    const int lrow = tid >> 2;
    const int lseg = tid & 3;
    const int p    = mblk * 128 + lrow;
    const int ab   = p >> 12;
    const int aoy  = ((p & 4095) >> 6) << 1;
    const int aox  = (p & 63) << 1;
    const int bgn  = nblk * 128 + lrow;
    const uint32_t a_dst = sb + lrow * 64 + (uint32_t)((lseg ^ ((lrow >> 1) & 3)) * 16);
    const uint32_t b_dst = a_dst + OFF_B;

    // A source base + validity for a tap
    auto tap_a = [&](int tap, const __half*& abase, uint32_t& vs) {
        const int dyr = (tap * 11) >> 5;             // tap / 3, exact for 0..8
        const int iy = aoy + dyr - 1;
        const int ix = aox + (tap - dyr * 3) - 1;
        const bool valid = ((unsigned)iy < 128u) && ((unsigned)ix < 128u);
        vs = valid ? 16u : 0u;
        const int cy = valid ? iy : 0, cx = valid ? ix : 0;
        abase = g_Ah + ((size_t)(((ab << 7) + cy) << 7) + cx) * CIN + lseg * 8;
    };
    auto issue = [&](const __half* abase, uint32_t vs, const __half* bbase,
                     int kc, uint32_t soff) {
        cp_async16z(a_dst + soff, abase + kc, vs);
        cp_async16(b_dst + soff, bbase + kc);
    };

    float acc[2][4][4];
    #pragma unroll
    for (int i = 0; i < 2; ++i)
        #pragma unroll
        for (int j = 0; j < 4; ++j)
            #pragma unroll
            for (int q = 0; q < 4; ++q) acc[i][j][q] = 0.f;

    // ---- ldsm addressing (loop-invariant offsets) ----
    const int arow_l = wm * 32 + (l & 15);
    const int a_rs   = (arow_l >> 1) & 3;
    const uint32_t a_base0 = sb + arow_l * 64;
    const int brow_l = wn * 32 + ((l >> 4) << 3) + (l & 7);
    const int b_rs   = (brow_l >> 1) & 3;
    const uint32_t b_base0 = sb + OFF_B + brow_l * 64;
    uint32_t a_off[2], b_off[2];
    #pragma unroll
    for (int k16 = 0; k16 < 2; ++k16) {
        a_off[k16] = (uint32_t)(((k16 * 2 + (l >> 4)) ^ a_rs) * 16);
        b_off[k16] = (uint32_t)(((k16 * 2 + ((l >> 3) & 1)) ^ b_rs) * 16);
    }

    // compute one chunk at stage offset soff (immediate after unroll)
    auto compute_chunk = [&](uint32_t soff) {
        #pragma unroll
        for (int k16 = 0; k16 < 2; ++k16) {
            uint32_t af[2][4], bh0[4], bh1[4];
            ldsm_x4(af[0][0], af[0][1], af[0][2], af[0][3],
                    a_base0 + a_off[k16] + soff);
            ldsm_x4(af[1][0], af[1][1], af[1][2], af[1][3],
                    a_base0 + 16 * 64 + a_off[k16] + soff);
            ldsm_x4(bh0[0], bh0[1], bh0[2], bh0[3], b_base0 + b_off[k16] + soff);
            ldsm_x4(bh1[0], bh1[1], bh1[2], bh1[3],
                    b_base0 + 16 * 64 + b_off[k16] + soff);
            #pragma unroll
            for (int mt = 0; mt < 2; ++mt)
                #pragma unroll
                for (int sub = 0; sub < 2; ++sub)
                    mma16816(acc[mt][sub], af[mt], bh0[sub * 2], bh0[sub * 2 + 1]);
            #pragma unroll
            for (int mt = 0; mt < 2; ++mt)
                #pragma unroll
                for (int sub = 0; sub < 2; ++sub)
                    mma16816(acc[mt][2 + sub], af[mt], bh1[sub * 2], bh1[sub * 2 + 1]);
        }
    };

    // ---- prologue: tap 0, chunks 0..3 into stages 0..3 (pairs 0,1) ----
    const __half* apf; uint32_t vpf;
    tap_a(0, apf, vpf);
    const __half* bpf = g_Wh + (size_t)bgn * K_TOTAL + lseg * 8;
    issue(apf, vpf, bpf, 0,  0);                cp_commit();
    issue(apf, vpf, bpf, 32, STAGE_BYTES);      cp_commit();
    issue(apf, vpf, bpf, 64, 2 * STAGE_BYTES);  cp_commit();
    issue(apf, vpf, bpf, 96, 3 * STAGE_BYTES);  cp_commit();

    // ---- main loop: 3 groups x 6 pairs (12 chunks each); stage = chunk%6 ----
    #pragma unroll 1
    for (int g = 0; g < 3; ++g) {
        #pragma unroll
        for (int pp = 0; pp < 6; ++pp) {
            // pair p = 6g+pp: compute chunks 12g+2pp, +1; prefetch chunks +4, +5
            cp_wait<2>();
            __syncthreads();       // all warps done with pair p-1 (its stages get refilled)

            // prefetch pair p+2's chunks (both in tap 3g + (pp+2)/2)
            const bool have = (pp < 4) || (g < 2);
            if ((pp & 1) == 0) {   // tap changes every other pair
                if (have) {
                    const int tap_pf = 3 * g + (pp + 2) / 2;
                    tap_a(tap_pf, apf, vpf);
                    bpf = g_Wh + (size_t)bgn * K_TOTAL + (size_t)tap_pf * 128 + lseg * 8;
                }
            }
            {
                const int kc0 = ((2 * pp + 4) & 3) * 32;           // immediate: 0 or 64
                const uint32_t s0 = (uint32_t)((2 * pp + 4) % 6) * STAGE_BYTES;
                const uint32_t s1 = (uint32_t)((2 * pp + 5) % 6) * STAGE_BYTES;
                if (have) issue(apf, vpf, bpf, kc0, s0);
                cp_commit();
                if (have) issue(apf, vpf, bpf, kc0 + 32, s1);
                cp_commit();
            }

            compute_chunk((uint32_t)((2 * pp) % 6) * STAGE_BYTES);
            compute_chunk((uint32_t)((2 * pp + 1) % 6) * STAGE_BYTES);
        }
    }

    // ---- epilogue ----
    const int row_base = mblk * 128 + wm * 32 + (l >> 2);
    const int col_base = nblk * 128 + wn * 32 + (l & 3) * 2;
    #pragma unroll
    for (int mt = 0; mt < 2; ++mt) {
        #pragma unroll
        for (int nt = 0; nt < 4; ++nt) {
            const int r0 = row_base + mt * 16;
            const int cc = col_base + nt * 8;
            float* o0 = out + (size_t)r0 * COUT + cc;
            float* o1 = out + (size_t)(r0 + 8) * COUT + cc;
            *reinterpret_cast<float2*>(o0) = make_float2(acc[mt][nt][0], acc[mt][nt][1]);
            *reinterpret_cast<float2*>(o1) = make_float2(acc[mt][nt][2], acc[mt][nt][3]);
        }
    }
}

// ---------------- launch ----------------
extern "C" void kernel_launch(void* const* d_in, const int* in_sizes, int n_in,
                              void* d_out, int out_size)
{
    const float* feats  = (const float*)d_in[0];
    const float* weight = (const float*)d_in[1];
    const float* alpha  = (const float*)d_in[2];
    float* out = (float*)d_out;

    cudaFuncSetAttribute(conv_mma_kernel,
                         cudaFuncAttributeMaxDynamicSharedMemorySize, SMEM_TOTAL);

    prep_kernel<<<A4_BLOCKS + W_BLOCKS + C_BLOCKS, 256>>>(feats, weight, alpha, out);
    dim3 grid(M_TOTAL / BM, COUT / BN);    // (256, 2)
    conv_mma_kernel<<<grid, NTHREADS, SMEM_TOTAL>>>(out);
}